// round 11
// baseline (speedup 1.0000x reference)
#include <cuda_runtime.h>
#include <cuda_bf16.h>
#include <math.h>

#define MAXB 4096
#define BLOCK 256
#define NWARP (BLOCK / 32)

// Named barriers (per-CTA): FULL = producers->consumer, FREE = consumer->producers.
#define BAR_FULL(p) (1 + (p))
#define BAR_FREE(p) (3 + (p))

// Per-row fixed-point partials + counters (zero-init; reset in-kernel each replay).
__device__ unsigned long long g_s[MAXB];    // sum(exp) * 2^33
__device__ unsigned long long g_t[MAXB];    // sum(x)   * 2^44 (two's complement)
__device__ unsigned int       g_cnt[MAXB];  // segments done
__device__ unsigned long long g_acc = 0ull; // total loss * 2^46
__device__ unsigned int       g_done = 0u;  // rows done

#define S_SCALE 8589934592.0          /* 2^33 */
#define T_SCALE 17592186044416.0      /* 2^44 */
#define FIXSCALE 70368744177664.0     /* 2^46 */

__device__ __forceinline__ void red_add_u64(unsigned long long* p, unsigned long long v) {
    asm volatile("red.relaxed.gpu.global.add.u64 [%0], %1;" :: "l"(p), "l"(v) : "memory");
}
__device__ __forceinline__ unsigned int atom_inc_acq_rel(unsigned int* p) {
    unsigned int old;
    asm volatile("atom.add.acq_rel.gpu.global.u32 %0, [%1], 1;"
                 : "=r"(old) : "l"(p) : "memory");
    return old;
}
__device__ __forceinline__ void bar_sync(int id)   { asm volatile("bar.sync %0, %1;"   :: "r"(id), "r"(BLOCK) : "memory"); }
__device__ __forceinline__ void bar_arrive(int id) { asm volatile("bar.arrive %0, %1;" :: "r"(id), "r"(BLOCK) : "memory"); }

// Persistent CTAs; each strides over half-row segments (64 KB). Per-segment
// reduce is pipelined: producer warps deposit warp partials into parity-
// double-buffered smem, bar.arrive, and stream on. Warp 0 consumes partials,
// fires the fence-free fixed-point combine (relaxed red.u64 + one acq_rel
// counter), and recycles the parity slot. No full-block drain anywhere.
__global__ __launch_bounds__(BLOCK, 8) void loss_kernel(
    const float* __restrict__ logits,
    const int* __restrict__ labels,
    int K, int B, int nseg,
    double coef_ce, double coef_kl,
    double tl_minus_toff, double toff, double C1,
    float* __restrict__ out)
{
    __shared__ float sm_s[2][NWARP];
    __shared__ float sm_t[2][NWARP];

    const int wid = threadIdx.x >> 5;
    const int lid = threadIdx.x & 31;
    const int n4  = K >> 2;         // 8000 float4/row
    const int hn  = n4 >> 1;        // 4000 float4/segment

    // Prime the FREE barriers: consumer pre-arrives both parities.
    if (wid == 0) { bar_arrive(BAR_FREE(0)); bar_arrive(BAR_FREE(1)); }

    int par = 0;
    for (int seg = blockIdx.x; seg < nseg; seg += gridDim.x, par ^= 1) {
        const int row  = seg >> 1;
        const int half = seg & 1;
        const int base = half * hn;
        const int end  = base + hn;

        const float4* __restrict__ rp =
            reinterpret_cast<const float4*>(logits + (size_t)row * (size_t)K);

        float s0 = 0.f, t0 = 0.f, s1 = 0.f, t1 = 0.f;
        int i = base + threadIdx.x;
        #pragma unroll 2
        for (; i + BLOCK < end; i += 2 * BLOCK) {
            float4 a = __ldcs(rp + i);
            float4 b = __ldcs(rp + i + BLOCK);
            s0 += __expf(a.x) + __expf(a.y) + __expf(a.z) + __expf(a.w);
            t0 += (a.x + a.y) + (a.z + a.w);
            s1 += __expf(b.x) + __expf(b.y) + __expf(b.z) + __expf(b.w);
            t1 += (b.x + b.y) + (b.z + b.w);
        }
        if (i < end) {
            float4 a = __ldcs(rp + i);
            s0 += __expf(a.x) + __expf(a.y) + __expf(a.z) + __expf(a.w);
            t0 += (a.x + a.y) + (a.z + a.w);
        }
        float s = s0 + s1;
        float t = t0 + t1;

        #pragma unroll
        for (int o = 16; o > 0; o >>= 1) {
            s += __shfl_down_sync(0xffffffffu, s, o);
            t += __shfl_down_sync(0xffffffffu, t, o);
        }

        if (wid != 0) {
            // Producer: wait slot free, deposit, signal, move on.
            bar_sync(BAR_FREE(par));
            if (lid == 0) { sm_s[par][wid] = s; sm_t[par][wid] = t; }
            __threadfence_block();
            bar_arrive(BAR_FULL(par));
        } else {
            // Consumer (also produces its own partial directly).
            if (lid == 0) { sm_s[par][0] = s; sm_t[par][0] = t; }
            bar_sync(BAR_FULL(par));
            __threadfence_block();
            if (lid == 0) {
                float s_tot = 0.f, t_tot = 0.f;
                #pragma unroll
                for (int w = 0; w < NWARP; w++) { s_tot += sm_s[par][w]; t_tot += sm_t[par][w]; }

                red_add_u64(&g_s[row], (unsigned long long)llround((double)s_tot * S_SCALE));
                red_add_u64(&g_t[row], (unsigned long long)llround((double)t_tot * T_SCALE));

                if (atom_inc_acq_rel(&g_cnt[row]) == 1u) {
                    const unsigned long long su = atomicAdd(&g_s[row], 0ull);
                    const unsigned long long tu = atomicAdd(&g_t[row], 0ull);
                    const double srow = (double)(long long)su * (1.0 / S_SCALE);
                    const double trow = (double)(long long)tu * (1.0 / T_SCALE);
                    atomicExch(&g_s[row], 0ull);
                    atomicExch(&g_t[row], 0ull);
                    atomicExch(&g_cnt[row], 0u);

                    int lab = labels[row];
                    if (lab < 0) lab = 0;
                    if (lab >= K) lab = K - 1;
                    const float xl = logits[(size_t)row * (size_t)K + (size_t)lab];

                    const double lse    = log(srow);
                    const double lp_lab = (double)xl - lse;
                    const double sumlp  = trow - (double)K * lse;
                    const double kl_row = C1 - (tl_minus_toff * lp_lab + toff * sumlp);
                    const double rl     = coef_ce * (-lp_lab) + coef_kl * kl_row;

                    red_add_u64(&g_acc, (unsigned long long)llround(rl * FIXSCALE));
                    if (atom_inc_acq_rel(&g_done) == (unsigned int)(B - 1)) {
                        const unsigned long long au = atomicAdd(&g_acc, 0ull);
                        out[0] = (float)((double)(long long)au * (1.0 / FIXSCALE));
                        atomicExch(&g_acc, 0ull);
                        atomicExch(&g_done, 0u);
                    }
                }
            }
            __syncwarp();
            bar_arrive(BAR_FREE(par));   // slot recycled
        }
    }
}

extern "C" void kernel_launch(void* const* d_in, const int* in_sizes, int n_in,
                              void* d_out, int out_size)
{
    int il = 0, ib = 1;
    if (n_in >= 2 && in_sizes[1] > in_sizes[0]) { il = 1; ib = 0; }

    const float* logits = (const float*)d_in[il];
    const int*   labels = (const int*)d_in[ib];
    float*       out    = (float*)d_out;

    const int B = in_sizes[ib];             // 4096
    const int K = in_sizes[il] / B;         // 32000
    const int nseg = B * 2;

    int sms = 148;
    cudaDeviceGetAttribute(&sms, cudaDevAttrMultiProcessorCount, 0);
    int grid = sms * 8;
    if (grid > nseg) grid = nseg;

    const double ALPHA = 0.95, TEMPERATURE = 20.0, MULTIPLIER = 1.0, CORRECT_PROB = 0.99;
    const double off_val = (1.0 - CORRECT_PROB) / (double)(K - 1);
    const double a  = CORRECT_PROB / TEMPERATURE;
    const double b  = off_val / TEMPERATURE;
    const double ea = exp(a), eb = exp(b);
    const double denom = ea + (double)(K - 1) * eb;
    const double tl    = ea / denom;
    const double toff  = eb / denom;
    const double C1    = tl * log(tl) + (double)(K - 1) * toff * log(toff);
    const double coef_ce = (1.0 - ALPHA) / (double)B;
    const double coef_kl = ALPHA * MULTIPLIER / ((double)B * (double)K);

    loss_kernel<<<grid, BLOCK>>>(logits, labels, K, B, nseg,
                                 coef_ce, coef_kl, tl - toff, toff, C1, out);
}

// round 12
// speedup vs baseline: 1.8818x; 1.8818x over previous
#include <cuda_runtime.h>
#include <cuda_bf16.h>
#include <math.h>

#define MAXB 4096
#define BLOCK 256
#define NWARP (BLOCK / 32)

// Per-row fixed-point partials + counters (zero-init; reset in-kernel each replay).
__device__ unsigned long long g_s[MAXB];    // sum(exp) * 2^33
__device__ unsigned long long g_t[MAXB];    // sum(x)   * 2^44 (two's complement)
__device__ unsigned int       g_cnt[MAXB];  // segments done
__device__ unsigned long long g_acc = 0ull; // total loss * 2^46
__device__ unsigned int       g_done = 0u;  // rows done

#define S_SCALE 8589934592.0          /* 2^33 */
#define T_SCALE 17592186044416.0      /* 2^44 */
#define FIXSCALE 70368744177664.0     /* 2^46 */

__device__ __forceinline__ void red_add_u64(unsigned long long* p, unsigned long long v) {
    asm volatile("red.relaxed.gpu.global.add.u64 [%0], %1;" :: "l"(p), "l"(v) : "memory");
}

__device__ __forceinline__ unsigned int atom_inc_acq_rel(unsigned int* p) {
    unsigned int old;
    asm volatile("atom.add.acq_rel.gpu.global.u32 %0, [%1], 1;"
                 : "=r"(old) : "l"(p) : "memory");
    return old;
}

__device__ __forceinline__ void warp_red2(float& s, float& t) {
    #pragma unroll
    for (int o = 16; o > 0; o >>= 1) {
        s += __shfl_down_sync(0xffffffffu, s, o);
        t += __shfl_down_sync(0xffffffffu, t, o);
    }
}

// One CTA per HALF-row (64 KB) — measured granularity optimum (R7/R9).
// Steady-state loop batches FOUR float4 loads per iteration (16 outstanding
// LDG.128 per thread), __ldcs evict-first. Fence-free deterministic
// fixed-point combine (relaxed red.u64 partials + one acq_rel counter).
__global__ __launch_bounds__(BLOCK) void seg_kernel(
    const float* __restrict__ logits,
    const int* __restrict__ labels,
    int K, int B,
    double coef_ce, double coef_kl,
    double tl_minus_toff, double toff, double C1,
    float* __restrict__ out)
{
    const int row  = blockIdx.x >> 1;
    const int half = blockIdx.x & 1;
    const int n4   = K >> 2;               // 8000 float4 per row
    const int hn   = n4 >> 1;              // 4000 per half
    const int base = half * hn;
    const int end  = base + hn;

    const float4* __restrict__ rp =
        reinterpret_cast<const float4*>(logits + (size_t)row * (size_t)K);

    float s0 = 0.f, t0 = 0.f, s1 = 0.f, t1 = 0.f;
    float s2 = 0.f, t2 = 0.f, s3 = 0.f, t3 = 0.f;
    int i = base + threadIdx.x;
    for (; i + 3 * BLOCK < end; i += 4 * BLOCK) {
        float4 a = __ldcs(rp + i);
        float4 b = __ldcs(rp + i + BLOCK);
        float4 c = __ldcs(rp + i + 2 * BLOCK);
        float4 d = __ldcs(rp + i + 3 * BLOCK);
        s0 += __expf(a.x) + __expf(a.y) + __expf(a.z) + __expf(a.w);
        t0 += (a.x + a.y) + (a.z + a.w);
        s1 += __expf(b.x) + __expf(b.y) + __expf(b.z) + __expf(b.w);
        t1 += (b.x + b.y) + (b.z + b.w);
        s2 += __expf(c.x) + __expf(c.y) + __expf(c.z) + __expf(c.w);
        t2 += (c.x + c.y) + (c.z + c.w);
        s3 += __expf(d.x) + __expf(d.y) + __expf(d.z) + __expf(d.w);
        t3 += (d.x + d.y) + (d.z + d.w);
    }
    for (; i < end; i += BLOCK) {
        float4 a = __ldcs(rp + i);
        s0 += __expf(a.x) + __expf(a.y) + __expf(a.z) + __expf(a.w);
        t0 += (a.x + a.y) + (a.z + a.w);
    }
    float s = (s0 + s1) + (s2 + s3);
    float t = (t0 + t1) + (t2 + t3);

    __shared__ float sm_s[NWARP];
    __shared__ float sm_t[NWARP];
    warp_red2(s, t);
    const int wid = threadIdx.x >> 5;
    const int lid = threadIdx.x & 31;
    if (lid == 0) { sm_s[wid] = s; sm_t[wid] = t; }
    __syncthreads();

    if (threadIdx.x == 0) {
        float s_tot = 0.f, t_tot = 0.f;
        #pragma unroll
        for (int w = 0; w < NWARP; w++) { s_tot += sm_s[w]; t_tot += sm_t[w]; }

        red_add_u64(&g_s[row], (unsigned long long)llround((double)s_tot * S_SCALE));
        red_add_u64(&g_t[row], (unsigned long long)llround((double)t_tot * T_SCALE));

        if (atom_inc_acq_rel(&g_cnt[row]) == 1u) {
            const unsigned long long su = atomicAdd(&g_s[row], 0ull);
            const unsigned long long tu = atomicAdd(&g_t[row], 0ull);
            const double srow = (double)(long long)su * (1.0 / S_SCALE);
            const double trow = (double)(long long)tu * (1.0 / T_SCALE);
            atomicExch(&g_s[row], 0ull);
            atomicExch(&g_t[row], 0ull);
            atomicExch(&g_cnt[row], 0u);

            int lab = labels[row];
            if (lab < 0) lab = 0;
            if (lab >= K) lab = K - 1;
            const float xl = logits[(size_t)row * (size_t)K + (size_t)lab];

            const double lse    = log(srow);
            const double lp_lab = (double)xl - lse;
            const double sumlp  = trow - (double)K * lse;
            const double kl_row = C1 - (tl_minus_toff * lp_lab + toff * sumlp);
            const double rl     = coef_ce * (-lp_lab) + coef_kl * kl_row;

            red_add_u64(&g_acc, (unsigned long long)llround(rl * FIXSCALE));
            if (atom_inc_acq_rel(&g_done) == (unsigned int)(B - 1)) {
                const unsigned long long au = atomicAdd(&g_acc, 0ull);
                out[0] = (float)((double)(long long)au * (1.0 / FIXSCALE));
                atomicExch(&g_acc, 0ull);
                atomicExch(&g_done, 0u);
            }
        }
    }
}

extern "C" void kernel_launch(void* const* d_in, const int* in_sizes, int n_in,
                              void* d_out, int out_size)
{
    int il = 0, ib = 1;
    if (n_in >= 2 && in_sizes[1] > in_sizes[0]) { il = 1; ib = 0; }

    const float* logits = (const float*)d_in[il];
    const int*   labels = (const int*)d_in[ib];
    float*       out    = (float*)d_out;

    const int B = in_sizes[ib];             // 4096
    const int K = in_sizes[il] / B;         // 32000

    const double ALPHA = 0.95, TEMPERATURE = 20.0, MULTIPLIER = 1.0, CORRECT_PROB = 0.99;
    const double off_val = (1.0 - CORRECT_PROB) / (double)(K - 1);
    const double a  = CORRECT_PROB / TEMPERATURE;
    const double b  = off_val / TEMPERATURE;
    const double ea = exp(a), eb = exp(b);
    const double denom = ea + (double)(K - 1) * eb;
    const double tl    = ea / denom;
    const double toff  = eb / denom;
    const double C1    = tl * log(tl) + (double)(K - 1) * toff * log(toff);
    const double coef_ce = (1.0 - ALPHA) / (double)B;
    const double coef_kl = ALPHA * MULTIPLIER / ((double)B * (double)K);

    seg_kernel<<<B * 2, BLOCK>>>(logits, labels, K, B,
                                 coef_ce, coef_kl, tl - toff, toff, C1, out);
}

// round 13
// speedup vs baseline: 2.0151x; 1.0708x over previous
#include <cuda_runtime.h>
#include <cuda_bf16.h>
#include <math.h>

#define MAXB 4096
#define BLOCK 256
#define NWARP (BLOCK / 32)

// Per-row state padded to a full 64B sector to avoid atomic sector ping-pong
// between finishing CTAs of adjacent rows. Zero-init; reset in-kernel.
struct __align__(64) RowState {
    unsigned long long s;    // sum(exp) * 2^33
    unsigned long long t;    // sum(x)   * 2^44 (two's complement)
    unsigned int cnt;        // segments done
    unsigned int pad[9];
};
__device__ RowState g_row[MAXB];
__device__ unsigned long long g_acc = 0ull; // total loss * 2^46
__device__ unsigned int       g_done = 0u;  // rows done

#define S_SCALE 8589934592.0          /* 2^33 */
#define T_SCALE 17592186044416.0      /* 2^44 */
#define FIXSCALE 70368744177664.0     /* 2^46 */

__device__ __forceinline__ void red_add_u64(unsigned long long* p, unsigned long long v) {
    asm volatile("red.relaxed.gpu.global.add.u64 [%0], %1;" :: "l"(p), "l"(v) : "memory");
}

__device__ __forceinline__ unsigned int atom_inc_acq_rel(unsigned int* p) {
    unsigned int old;
    asm volatile("atom.add.acq_rel.gpu.global.u32 %0, [%1], 1;"
                 : "=r"(old) : "l"(p) : "memory");
    return old;
}

__device__ __forceinline__ void warp_red2(float& s, float& t) {
    #pragma unroll
    for (int o = 16; o > 0; o >>= 1) {
        s += __shfl_down_sync(0xffffffffu, s, o);
        t += __shfl_down_sync(0xffffffffu, t, o);
    }
}

// One CTA per HALF-row (64 KB), 256 threads, unroll-2 (8 outstanding LDG.128
// per thread) — the measured optimum (R9: 82.1us, DRAM 80.8%).
// __launch_bounds__(256, 8) pins regs <= 32 so 8 CTAs/SM always fit.
// Fence-free deterministic fixed-point combine.
__global__ __launch_bounds__(BLOCK, 8) void seg_kernel(
    const float* __restrict__ logits,
    const int* __restrict__ labels,
    int K, int B,
    double coef_ce, double coef_kl,
    double tl_minus_toff, double toff, double C1,
    float* __restrict__ out)
{
    const int row  = blockIdx.x >> 1;
    const int half = blockIdx.x & 1;
    const int n4   = K >> 2;               // 8000 float4 per row
    const int hn   = n4 >> 1;              // 4000 per half
    const int base = half * hn;
    const int end  = base + hn;

    const float4* __restrict__ rp =
        reinterpret_cast<const float4*>(logits + (size_t)row * (size_t)K);

    float s0 = 0.f, t0 = 0.f, s1 = 0.f, t1 = 0.f;
    int i = base + threadIdx.x;
    #pragma unroll 2
    for (; i + BLOCK < end; i += 2 * BLOCK) {
        float4 a = __ldcs(rp + i);
        float4 b = __ldcs(rp + i + BLOCK);
        s0 += __expf(a.x) + __expf(a.y) + __expf(a.z) + __expf(a.w);
        t0 += (a.x + a.y) + (a.z + a.w);
        s1 += __expf(b.x) + __expf(b.y) + __expf(b.z) + __expf(b.w);
        t1 += (b.x + b.y) + (b.z + b.w);
    }
    if (i < end) {
        float4 a = __ldcs(rp + i);
        s0 += __expf(a.x) + __expf(a.y) + __expf(a.z) + __expf(a.w);
        t0 += (a.x + a.y) + (a.z + a.w);
    }
    float s = s0 + s1;
    float t = t0 + t1;

    __shared__ float sm_s[NWARP];
    __shared__ float sm_t[NWARP];
    warp_red2(s, t);
    const int wid = threadIdx.x >> 5;
    const int lid = threadIdx.x & 31;
    if (lid == 0) { sm_s[wid] = s; sm_t[wid] = t; }
    __syncthreads();

    if (threadIdx.x == 0) {
        float s_tot = 0.f, t_tot = 0.f;
        #pragma unroll
        for (int w = 0; w < NWARP; w++) { s_tot += sm_s[w]; t_tot += sm_t[w]; }

        RowState* rs = &g_row[row];
        red_add_u64(&rs->s, (unsigned long long)llround((double)s_tot * S_SCALE));
        red_add_u64(&rs->t, (unsigned long long)llround((double)t_tot * T_SCALE));

        if (atom_inc_acq_rel(&rs->cnt) == 1u) {
            const unsigned long long su = atomicAdd(&rs->s, 0ull);
            const unsigned long long tu = atomicAdd(&rs->t, 0ull);
            const double srow = (double)(long long)su * (1.0 / S_SCALE);
            const double trow = (double)(long long)tu * (1.0 / T_SCALE);
            atomicExch(&rs->s, 0ull);
            atomicExch(&rs->t, 0ull);
            atomicExch(&rs->cnt, 0u);

            int lab = labels[row];
            if (lab < 0) lab = 0;
            if (lab >= K) lab = K - 1;
            const float xl = logits[(size_t)row * (size_t)K + (size_t)lab];

            const double lse    = log(srow);
            const double lp_lab = (double)xl - lse;
            const double sumlp  = trow - (double)K * lse;
            const double kl_row = C1 - (tl_minus_toff * lp_lab + toff * sumlp);
            const double rl     = coef_ce * (-lp_lab) + coef_kl * kl_row;

            red_add_u64(&g_acc, (unsigned long long)llround(rl * FIXSCALE));
            if (atom_inc_acq_rel(&g_done) == (unsigned int)(B - 1)) {
                const unsigned long long au = atomicAdd(&g_acc, 0ull);
                out[0] = (float)((double)(long long)au * (1.0 / FIXSCALE));
                atomicExch(&g_acc, 0ull);
                atomicExch(&g_done, 0u);
            }
        }
    }
}

extern "C" void kernel_launch(void* const* d_in, const int* in_sizes, int n_in,
                              void* d_out, int out_size)
{
    int il = 0, ib = 1;
    if (n_in >= 2 && in_sizes[1] > in_sizes[0]) { il = 1; ib = 0; }

    const float* logits = (const float*)d_in[il];
    const int*   labels = (const int*)d_in[ib];
    float*       out    = (float*)d_out;

    const int B = in_sizes[ib];             // 4096
    const int K = in_sizes[il] / B;         // 32000

    const double ALPHA = 0.95, TEMPERATURE = 20.0, MULTIPLIER = 1.0, CORRECT_PROB = 0.99;
    const double off_val = (1.0 - CORRECT_PROB) / (double)(K - 1);
    const double a  = CORRECT_PROB / TEMPERATURE;
    const double b  = off_val / TEMPERATURE;
    const double ea = exp(a), eb = exp(b);
    const double denom = ea + (double)(K - 1) * eb;
    const double tl    = ea / denom;
    const double toff  = eb / denom;
    const double C1    = tl * log(tl) + (double)(K - 1) * toff * log(toff);
    const double coef_ce = (1.0 - ALPHA) / (double)B;
    const double coef_kl = ALPHA * MULTIPLIER / ((double)B * (double)K);

    seg_kernel<<<B * 2, BLOCK>>>(logits, labels, K, B,
                                 coef_ce, coef_kl, tl - toff, toff, C1, out);
}